// round 14
// baseline (speedup 1.0000x reference)
#include <cuda_runtime.h>
#include <cstdint>

// YoloLoss: N=4096, S=14, B=2, NUM_CLS=20.
// Double-buffered TMA pipeline: each block processes 4 tiles x 128 cells,
// 2 x 28160B smem buffers; tile t+1's cp.async.bulk is in flight while
// tile t computes. 5 pre-scaled fire-and-forget REDs into d_out at the
// end; graph memset node zeroes d_out. NO gpu-scope fences (R3/R5/R7).
// inputs: pred (N,S,S,30) f32, tbox (N,S,S,4) f32, tcls (N,S,S,20) f32,
//         mask (N,S,S) int32;  output: 5 f32.

static constexpr int NSAMP = 4096;
static constexpr int S2    = 14 * 14;
static constexpr int NCELL = NSAMP * S2;     // 802816
static constexpr int TILE  = 128;            // cells per tile (== threads)
static constexpr int TPB   = 4;              // tiles per block
static constexpr int CELLS = TILE * TPB;     // 512 cells per block
static constexpr int NBLK  = NCELL / CELLS;  // 1568

static constexpr uint32_t PRED_B = TILE * 30 * 4;  // 15360
static constexpr uint32_t TCLS_B = TILE * 20 * 4;  // 10240
static constexpr uint32_t TBOX_B = TILE * 4 * 4;   //  2048
static constexpr uint32_t MASK_B = TILE * 4;       //   512
static constexpr uint32_t BUF_B  = PRED_B + TCLS_B + TBOX_B + MASK_B; // 28160

static constexpr uint32_t OFF_TCLS = PRED_B;            // 15360
static constexpr uint32_t OFF_TBOX = PRED_B + TCLS_B;   // 25600
static constexpr uint32_t OFF_MASK = OFF_TBOX + TBOX_B; // 27648
static constexpr uint32_t OFF_MBAR = 2 * BUF_B;         // 56320
static constexpr uint32_t OFF_RED  = OFF_MBAR + 16;     // 56336
static constexpr uint32_t SMEM_TOTAL = OFF_RED + 64;    // 56400

__device__ __forceinline__ uint32_t s2u(const void* p) {
    uint32_t a;
    asm("{ .reg .u64 t; cvta.to.shared.u64 t, %1; cvt.u32.u64 %0, t; }"
        : "=r"(a) : "l"(p));
    return a;
}

__device__ __forceinline__ void tma_issue(
    uint32_t buf, uint32_t mb,
    const float* pred, const float* tbox, const float* tcls, const int* mask,
    long cell0)
{
    asm volatile("mbarrier.arrive.expect_tx.shared.b64 _, [%0], %1;"
                 :: "r"(mb), "r"(BUF_B) : "memory");
    asm volatile("cp.async.bulk.shared::cta.global.mbarrier::complete_tx::bytes "
                 "[%0], [%1], %2, [%3];"
                 :: "r"(buf), "l"(pred + cell0 * 30), "r"(PRED_B), "r"(mb) : "memory");
    asm volatile("cp.async.bulk.shared::cta.global.mbarrier::complete_tx::bytes "
                 "[%0], [%1], %2, [%3];"
                 :: "r"(buf + OFF_TCLS), "l"(tcls + cell0 * 20), "r"(TCLS_B), "r"(mb) : "memory");
    asm volatile("cp.async.bulk.shared::cta.global.mbarrier::complete_tx::bytes "
                 "[%0], [%1], %2, [%3];"
                 :: "r"(buf + OFF_TBOX), "l"(tbox + cell0 * 4), "r"(TBOX_B), "r"(mb) : "memory");
    asm volatile("cp.async.bulk.shared::cta.global.mbarrier::complete_tx::bytes "
                 "[%0], [%1], %2, [%3];"
                 :: "r"(buf + OFF_MASK), "l"(mask + cell0), "r"(MASK_B), "r"(mb) : "memory");
}

__global__ __launch_bounds__(TILE) void yolo_k(
    const float* __restrict__ pred,
    const float* __restrict__ tbox,
    const float* __restrict__ tcls,
    const int* __restrict__ mask,
    float* __restrict__ out)
{
    extern __shared__ char dsm[];
    const uint32_t sbase = s2u(dsm);
    const uint32_t mb0 = sbase + OFF_MBAR;
    const uint32_t mb1 = sbase + OFF_MBAR + 8;
    float* red = reinterpret_cast<float*>(dsm + OFF_RED);

    const int tid = threadIdx.x;
    const long blk0 = (long)blockIdx.x * CELLS;

    if (tid == 0) {
        asm volatile("mbarrier.init.shared.b64 [%0], %1;" :: "r"(mb0), "r"(1u) : "memory");
        asm volatile("mbarrier.init.shared.b64 [%0], %1;" :: "r"(mb1), "r"(1u) : "memory");
    }
    __syncthreads();

    if (tid == 0) {
        tma_issue(sbase,         mb0, pred, tbox, tcls, mask, blk0);
        tma_issue(sbase + BUF_B, mb1, pred, tbox, tcls, mask, blk0 + TILE);
    }

    const float invS = 1.0f / 14.0f;
    float acc0 = 0.f, acc1 = 0.f, acc2 = 0.f, acc3 = 0.f;

#pragma unroll
    for (int t = 0; t < TPB; t++) {
        const int b = t & 1;
        const uint32_t mb = b ? mb1 : mb0;
        const uint32_t par = (t >> 1) & 1;          // buffer's use-count parity
        const char* buf = dsm + b * BUF_B;

        // wait for this tile's data (acquire -> orders smem reads after)
        {
            uint32_t done;
            do {
                asm volatile(
                    "{\n\t.reg .pred p;\n\t"
                    "mbarrier.try_wait.parity.acquire.cta.shared::cta.b64 p, [%1], %2, 0x989680;\n\t"
                    "selp.b32 %0, 1, 0, p;\n\t}"
                    : "=r"(done) : "r"(mb), "r"(par) : "memory");
            } while (!done);
        }

        const float2* Pb = reinterpret_cast<const float2*>(buf) + tid * 15;
        const float4* Tc = reinterpret_cast<const float4*>(buf + OFF_TCLS) + tid * 5;
        const float4  tb = reinterpret_cast<const float4*>(buf + OFF_TBOX)[tid];
        const int     mi = reinterpret_cast<const int*>(buf + OFF_MASK)[tid];
        const float   m  = (mi != 0) ? 1.0f : 0.0f;

        float2 p01 = Pb[0], p23 = Pb[1], p45 = Pb[2], p67 = Pb[3], p89 = Pb[4];

        float cls = 0.0f;
#pragma unroll
        for (int q = 0; q < 5; q++) {
            float4 tv = Tc[q];
            float2 a = Pb[5 + 2 * q];
            float2 c = Pb[6 + 2 * q];
            float d0 = a.x - tv.x, d1 = a.y - tv.y;
            float d2 = c.x - tv.z, d3 = c.y - tv.w;
            cls += d0 * d0 + d1 * d1 + d2 * d2 + d3 * d3;
        }
        acc3 += cls * m;

        // box0: x=p01.x y=p01.y w=p23.x h=p23.y conf=p45.x
        // box1: x=p45.y y=p67.x w=p67.y h=p89.x conf=p89.y
        acc2 += (p45.x * p45.x + p89.y * p89.y) * (1.0f - m);

        float gx1 = tb.x * invS - 0.5f * tb.z, gx2 = tb.x * invS + 0.5f * tb.z;
        float gy1 = tb.y * invS - 0.5f * tb.w, gy2 = tb.y * invS + 0.5f * tb.w;
        float area_g = (gx2 - gx1) * (gy2 - gy1);

        float bxv[2] = {p01.x, p45.y};
        float byv[2] = {p01.y, p67.x};
        float bwv[2] = {p23.x, p67.y};
        float bhv[2] = {p23.y, p89.x};
        float bcv[2] = {p45.x, p89.y};

        float iou0, iou1;
#pragma unroll
        for (int bb = 0; bb < 2; bb++) {
            float px1 = bxv[bb] * invS - 0.5f * bwv[bb];
            float px2 = bxv[bb] * invS + 0.5f * bwv[bb];
            float py1 = byv[bb] * invS - 0.5f * bhv[bb];
            float py2 = byv[bb] * invS + 0.5f * bhv[bb];
            float iw = fmaxf(fminf(px2, gx2) - fmaxf(px1, gx1), 0.0f);
            float ih = fmaxf(fminf(py2, gy2) - fmaxf(py1, gy1), 0.0f);
            float inter  = iw * ih;
            float area_p = (px2 - px1) * (py2 - py1);
            float v = inter / (area_p + area_g - inter);
            if (bb == 0) iou0 = v; else iou1 = v;
        }
        // jnp.argmax keeps first max on ties -> strict '>' for box 1
        const bool sel1 = (iou1 > iou0);
        const float bx = sel1 ? bxv[1] : bxv[0];
        const float by = sel1 ? byv[1] : byv[0];
        const float bw = sel1 ? bwv[1] : bwv[0];
        const float bh = sel1 ? bhv[1] : bhv[0];
        const float bc = sel1 ? bcv[1] : bcv[0];

        float dx = bx - tb.x, dy = by - tb.y;
        float dw = sqrtf(bw) - sqrtf(tb.z);
        float dh = sqrtf(bh) - sqrtf(tb.w);
        acc0 += (dx * dx + dy * dy + dw * dw + dh * dh) * m;
        float dc = bc - 1.0f;
        acc1 += dc * dc * m;

        // all threads done reading buffer b -> safe to refill
        __syncthreads();
        if (t + 2 < TPB && tid == 0) {
            tma_issue(sbase + b * BUF_B, mb, pred, tbox, tcls, mask,
                      blk0 + (long)(t + 2) * TILE);
        }
    }

    // --- reduction: warp shuffle -> smem -> 5 pre-scaled REDs into d_out ---
    float v0 = acc0, v1 = acc1, v2 = acc2, v3 = acc3;
#pragma unroll
    for (int off = 16; off > 0; off >>= 1) {
        v0 += __shfl_xor_sync(0xffffffffu, v0, off);
        v1 += __shfl_xor_sync(0xffffffffu, v1, off);
        v2 += __shfl_xor_sync(0xffffffffu, v2, off);
        v3 += __shfl_xor_sync(0xffffffffu, v3, off);
    }
    const int warp = tid >> 5;
    if ((tid & 31) == 0) {
        red[warp * 4 + 0] = v0; red[warp * 4 + 1] = v1;
        red[warp * 4 + 2] = v2; red[warp * 4 + 3] = v3;
    }
    __syncthreads();
    if (tid < 5) {
        float s0 = red[0] + red[4] + red[8]  + red[12]; // reg raw
        float s1 = red[1] + red[5] + red[9]  + red[13]; // contain
        float s2 = red[2] + red[6] + red[10] + red[14]; // noobj raw
        float s3 = red[3] + red[7] + red[11] + red[15]; // cls
        const float invN = 1.0f / (float)NSAMP;
        float val;
        switch (tid) {
            case 0: val = (5.0f * s0 + s1 + 0.5f * s2 + s3) * invN; break;
            case 1: val = 5.0f * s0 * invN; break;
            case 2: val = s1 * invN; break;
            case 3: val = 0.5f * s2 * invN; break;
            default: val = s3 * invN; break;
        }
        atomicAdd(&out[tid], val);   // return unused -> RED, no ordering op
    }
}

extern "C" void kernel_launch(void* const* d_in, const int* in_sizes, int n_in,
                              void* d_out, int out_size)
{
    const float* pred = (const float*)d_in[0];
    const float* tbox = (const float*)d_in[1];
    const float* tcls = (const float*)d_in[2];
    const int*   mask = (const int*)d_in[3];
    float* out = (float*)d_out;

    static bool attr_set = false;
    if (!attr_set) {
        cudaFuncSetAttribute(yolo_k, cudaFuncAttributeMaxDynamicSharedMemorySize,
                             SMEM_TOTAL);
        attr_set = true;
    }

    // graph memset node: zero the 5 output floats each replay (REDs add onto it)
    cudaMemsetAsync(out, 0, 5 * sizeof(float), 0);
    yolo_k<<<NBLK, TILE, SMEM_TOTAL>>>(pred, tbox, tcls, mask, out);
}

// round 15
// speedup vs baseline: 1.0029x; 1.0029x over previous
#include <cuda_runtime.h>
#include <cstdint>

// YoloLoss: N=4096, S=14, B=2, NUM_CLS=20.
// PERSISTENT double-buffered TMA pipeline: 608 blocks (4/SM x 152 SMs),
// each strides over ~10 tiles of 128 cells with 2 x 28160B smem buffers;
// the next tile's cp.async.bulk is always in flight during compute and the
// pipeline never drains between tiles (kills per-block prologue bubbles).
// Tail: 5 pre-scaled fire-and-forget REDs into d_out; graph memset node
// zeroes d_out each replay. NO gpu-scope fences (R3/R5/R7: +15us).
// inputs: pred (N,S,S,30) f32, tbox (N,S,S,4) f32, tcls (N,S,S,20) f32,
//         mask (N,S,S) int32;  output: 5 f32.

static constexpr int NSAMP = 4096;
static constexpr int S2    = 14 * 14;
static constexpr int NCELL = NSAMP * S2;     // 802816
static constexpr int TILE  = 128;            // cells per tile (== threads)
static constexpr int NTILE = NCELL / TILE;   // 6272
static constexpr int GRID  = 608;            // 4 blocks/SM x 152 SMs

static constexpr uint32_t PRED_B = TILE * 30 * 4;  // 15360
static constexpr uint32_t TCLS_B = TILE * 20 * 4;  // 10240
static constexpr uint32_t TBOX_B = TILE * 4 * 4;   //  2048
static constexpr uint32_t MASK_B = TILE * 4;       //   512
static constexpr uint32_t BUF_B  = PRED_B + TCLS_B + TBOX_B + MASK_B; // 28160

static constexpr uint32_t OFF_TCLS = PRED_B;            // 15360
static constexpr uint32_t OFF_TBOX = PRED_B + TCLS_B;   // 25600
static constexpr uint32_t OFF_MASK = OFF_TBOX + TBOX_B; // 27648
static constexpr uint32_t OFF_MBAR = 2 * BUF_B;         // 56320
static constexpr uint32_t OFF_RED  = OFF_MBAR + 16;     // 56336
static constexpr uint32_t SMEM_TOTAL = OFF_RED + 64;    // 56400

__device__ __forceinline__ uint32_t s2u(const void* p) {
    uint32_t a;
    asm("{ .reg .u64 t; cvta.to.shared.u64 t, %1; cvt.u32.u64 %0, t; }"
        : "=r"(a) : "l"(p));
    return a;
}

__device__ __forceinline__ void tma_issue(
    uint32_t buf, uint32_t mb,
    const float* pred, const float* tbox, const float* tcls, const int* mask,
    long cell0)
{
    asm volatile("mbarrier.arrive.expect_tx.shared.b64 _, [%0], %1;"
                 :: "r"(mb), "r"(BUF_B) : "memory");
    asm volatile("cp.async.bulk.shared::cta.global.mbarrier::complete_tx::bytes "
                 "[%0], [%1], %2, [%3];"
                 :: "r"(buf), "l"(pred + cell0 * 30), "r"(PRED_B), "r"(mb) : "memory");
    asm volatile("cp.async.bulk.shared::cta.global.mbarrier::complete_tx::bytes "
                 "[%0], [%1], %2, [%3];"
                 :: "r"(buf + OFF_TCLS), "l"(tcls + cell0 * 20), "r"(TCLS_B), "r"(mb) : "memory");
    asm volatile("cp.async.bulk.shared::cta.global.mbarrier::complete_tx::bytes "
                 "[%0], [%1], %2, [%3];"
                 :: "r"(buf + OFF_TBOX), "l"(tbox + cell0 * 4), "r"(TBOX_B), "r"(mb) : "memory");
    asm volatile("cp.async.bulk.shared::cta.global.mbarrier::complete_tx::bytes "
                 "[%0], [%1], %2, [%3];"
                 :: "r"(buf + OFF_MASK), "l"(mask + cell0), "r"(MASK_B), "r"(mb) : "memory");
}

__global__ __launch_bounds__(TILE) void yolo_k(
    const float* __restrict__ pred,
    const float* __restrict__ tbox,
    const float* __restrict__ tcls,
    const int* __restrict__ mask,
    float* __restrict__ out)
{
    extern __shared__ char dsm[];
    const uint32_t sbase = s2u(dsm);
    const uint32_t mb0 = sbase + OFF_MBAR;
    const uint32_t mb1 = sbase + OFF_MBAR + 8;
    float* red = reinterpret_cast<float*>(dsm + OFF_RED);

    const int tid = threadIdx.x;
    const int bid = blockIdx.x;

    // tiles for this block: bid, bid+GRID, bid+2*GRID, ...
    const int nt = (NTILE - bid + GRID - 1) / GRID;

    if (tid == 0) {
        asm volatile("mbarrier.init.shared.b64 [%0], %1;" :: "r"(mb0), "r"(1u) : "memory");
        asm volatile("mbarrier.init.shared.b64 [%0], %1;" :: "r"(mb1), "r"(1u) : "memory");
    }
    __syncthreads();

    if (tid == 0) {
        tma_issue(sbase, mb0, pred, tbox, tcls, mask, (long)bid * TILE);
        if (nt > 1)
            tma_issue(sbase + BUF_B, mb1, pred, tbox, tcls, mask,
                      (long)(bid + GRID) * TILE);
    }

    const float invS = 1.0f / 14.0f;
    float acc0 = 0.f, acc1 = 0.f, acc2 = 0.f, acc3 = 0.f;

    for (int i = 0; i < nt; i++) {
        const int b = i & 1;
        const uint32_t mb = b ? mb1 : mb0;
        const uint32_t par = (i >> 1) & 1;          // buffer's use-count parity
        const char* buf = dsm + b * BUF_B;

        // wait for this tile's data (acquire -> orders smem reads after)
        {
            uint32_t done;
            do {
                asm volatile(
                    "{\n\t.reg .pred p;\n\t"
                    "mbarrier.try_wait.parity.acquire.cta.shared::cta.b64 p, [%1], %2, 0x989680;\n\t"
                    "selp.b32 %0, 1, 0, p;\n\t}"
                    : "=r"(done) : "r"(mb), "r"(par) : "memory");
            } while (!done);
        }

        const float2* Pb = reinterpret_cast<const float2*>(buf) + tid * 15;
        const float4* Tc = reinterpret_cast<const float4*>(buf + OFF_TCLS) + tid * 5;
        const float4  tb = reinterpret_cast<const float4*>(buf + OFF_TBOX)[tid];
        const int     mi = reinterpret_cast<const int*>(buf + OFF_MASK)[tid];
        const float   m  = (mi != 0) ? 1.0f : 0.0f;

        float2 p01 = Pb[0], p23 = Pb[1], p45 = Pb[2], p67 = Pb[3], p89 = Pb[4];

        float cls = 0.0f;
#pragma unroll
        for (int q = 0; q < 5; q++) {
            float4 tv = Tc[q];
            float2 a = Pb[5 + 2 * q];
            float2 c = Pb[6 + 2 * q];
            float d0 = a.x - tv.x, d1 = a.y - tv.y;
            float d2 = c.x - tv.z, d3 = c.y - tv.w;
            cls += d0 * d0 + d1 * d1 + d2 * d2 + d3 * d3;
        }
        acc3 += cls * m;

        // box0: x=p01.x y=p01.y w=p23.x h=p23.y conf=p45.x
        // box1: x=p45.y y=p67.x w=p67.y h=p89.x conf=p89.y
        acc2 += (p45.x * p45.x + p89.y * p89.y) * (1.0f - m);

        float gx1 = tb.x * invS - 0.5f * tb.z, gx2 = tb.x * invS + 0.5f * tb.z;
        float gy1 = tb.y * invS - 0.5f * tb.w, gy2 = tb.y * invS + 0.5f * tb.w;
        float area_g = (gx2 - gx1) * (gy2 - gy1);

        float bxv[2] = {p01.x, p45.y};
        float byv[2] = {p01.y, p67.x};
        float bwv[2] = {p23.x, p67.y};
        float bhv[2] = {p23.y, p89.x};
        float bcv[2] = {p45.x, p89.y};

        float iou0, iou1;
#pragma unroll
        for (int bb = 0; bb < 2; bb++) {
            float px1 = bxv[bb] * invS - 0.5f * bwv[bb];
            float px2 = bxv[bb] * invS + 0.5f * bwv[bb];
            float py1 = byv[bb] * invS - 0.5f * bhv[bb];
            float py2 = byv[bb] * invS + 0.5f * bhv[bb];
            float iw = fmaxf(fminf(px2, gx2) - fmaxf(px1, gx1), 0.0f);
            float ih = fmaxf(fminf(py2, gy2) - fmaxf(py1, gy1), 0.0f);
            float inter  = iw * ih;
            float area_p = (px2 - px1) * (py2 - py1);
            float v = inter / (area_p + area_g - inter);
            if (bb == 0) iou0 = v; else iou1 = v;
        }
        // jnp.argmax keeps first max on ties -> strict '>' for box 1
        const bool sel1 = (iou1 > iou0);
        const float bx = sel1 ? bxv[1] : bxv[0];
        const float by = sel1 ? byv[1] : byv[0];
        const float bw = sel1 ? bwv[1] : bwv[0];
        const float bh = sel1 ? bhv[1] : bhv[0];
        const float bc = sel1 ? bcv[1] : bcv[0];

        float dx = bx - tb.x, dy = by - tb.y;
        float dw = sqrtf(bw) - sqrtf(tb.z);
        float dh = sqrtf(bh) - sqrtf(tb.w);
        acc0 += (dx * dx + dy * dy + dw * dw + dh * dh) * m;
        float dc = bc - 1.0f;
        acc1 += dc * dc * m;

        // all threads done reading buffer b -> safe to refill
        __syncthreads();
        if (i + 2 < nt && tid == 0) {
            tma_issue(sbase + b * BUF_B, mb, pred, tbox, tcls, mask,
                      (long)(bid + (i + 2) * GRID) * TILE);
        }
    }

    // --- reduction: warp shuffle -> smem -> 5 pre-scaled REDs into d_out ---
    float v0 = acc0, v1 = acc1, v2 = acc2, v3 = acc3;
#pragma unroll
    for (int off = 16; off > 0; off >>= 1) {
        v0 += __shfl_xor_sync(0xffffffffu, v0, off);
        v1 += __shfl_xor_sync(0xffffffffu, v1, off);
        v2 += __shfl_xor_sync(0xffffffffu, v2, off);
        v3 += __shfl_xor_sync(0xffffffffu, v3, off);
    }
    const int warp = tid >> 5;
    if ((tid & 31) == 0) {
        red[warp * 4 + 0] = v0; red[warp * 4 + 1] = v1;
        red[warp * 4 + 2] = v2; red[warp * 4 + 3] = v3;
    }
    __syncthreads();
    if (tid < 5) {
        float s0 = red[0] + red[4] + red[8]  + red[12]; // reg raw
        float s1 = red[1] + red[5] + red[9]  + red[13]; // contain
        float s2 = red[2] + red[6] + red[10] + red[14]; // noobj raw
        float s3 = red[3] + red[7] + red[11] + red[15]; // cls
        const float invN = 1.0f / (float)NSAMP;
        float val;
        switch (tid) {
            case 0: val = (5.0f * s0 + s1 + 0.5f * s2 + s3) * invN; break;
            case 1: val = 5.0f * s0 * invN; break;
            case 2: val = s1 * invN; break;
            case 3: val = 0.5f * s2 * invN; break;
            default: val = s3 * invN; break;
        }
        atomicAdd(&out[tid], val);   // return unused -> RED, no ordering op
    }
}

extern "C" void kernel_launch(void* const* d_in, const int* in_sizes, int n_in,
                              void* d_out, int out_size)
{
    const float* pred = (const float*)d_in[0];
    const float* tbox = (const float*)d_in[1];
    const float* tcls = (const float*)d_in[2];
    const int*   mask = (const int*)d_in[3];
    float* out = (float*)d_out;

    cudaFuncSetAttribute(yolo_k, cudaFuncAttributeMaxDynamicSharedMemorySize,
                         SMEM_TOTAL);

    // graph memset node: zero the 5 output floats each replay (REDs add onto it)
    cudaMemsetAsync(out, 0, 5 * sizeof(float), 0);
    yolo_k<<<GRID, TILE, SMEM_TOTAL>>>(pred, tbox, tcls, mask, out);
}